// round 12
// baseline (speedup 1.0000x reference)
#include <cuda_runtime.h>
#include <cuda_bf16.h>
#include <mma.h>
#include <cstdint>

using namespace nvcuda;

#define Bsz 64
#define Ssz 64
#define Hsz 1024
#define Vsz 32000
#define Tsz 40
#define NBLK 148
#define NTHR 256

// ---------------- scratch ----------------
__device__ float g_keysU[Bsz * Ssz * Hsz];          // 16 MB (bias added in persist)
__device__ float g_emb[Tsz * Bsz * Hsz];            // 10 MB [t][b][h] (tf32-rounded)
__device__ float g_h[Bsz * Hsz];                    // exact fp32 hidden
__device__ float g_h32[Bsz * Hsz];                  // tf32-rounded copy for GEMMs
__device__ float g_q4[4][Bsz * Hsz];                // q split-K parts
__device__ float g_gh2[2][Bsz * 3 * Hsz];           // gh split-K parts (K=512 x2)
__device__ float g_gc4[4][Bsz * 3 * Hsz];           // gi ctx-half split-K parts
__device__ float g_giE[(size_t)Tsz * Bsz * 3 * Hsz];// 31.5 MB
__device__ float g_ctx[Bsz * Hsz];                  // tf32-rounded at store
__device__ float g_sc[Bsz * Ssz];                   // attention scores
__device__ __nv_bfloat16 g_hall[Tsz * Bsz * Hsz];   // 5 MB
__device__ __nv_bfloat16 g_wout[Vsz * Hsz];         // 65 MB
// tf32-RN pre-rounded operand copies
__device__ float g_enc32[Bsz * Ssz * Hsz];          // 16 MB
__device__ float g_Ua32[Hsz * Hsz];
__device__ float g_Wa32[Hsz * Hsz];
__device__ float g_Whh32[3 * Hsz * Hsz];
__device__ float g_Wih32[3 * Hsz * 2 * Hsz];
__device__ unsigned g_barcnt = 0;
__device__ unsigned g_bargen = 0;
// dependency channels
__device__ unsigned g_ccnt[8];
__device__ volatile unsigned g_cgen[8];
#define CH_Q 0
#define CH_CTX 1
#define CH_D 2
#define CH_GH 3
#define CH_H 4
#define CH_SC 5

// fast activations
__device__ __forceinline__ float tanh_fast(float x) {
    float y; asm("tanh.approx.f32 %0, %1;" : "=f"(y) : "f"(x)); return y;
}
__device__ __forceinline__ float ftanh(float x) {
    float e = __expf(2.f * x);
    return 1.f - __fdividef(2.f, e + 1.f);
}
__device__ __forceinline__ float fsigmoid(float x) {
    return __fdividef(1.f, 1.f + __expf(-x));
}
__device__ __forceinline__ float rnd32(float x) {
    float y; asm("cvt.rna.tf32.f32 %0, %1;" : "=f"(y) : "f"(x)); return y;
}

// cp.async helpers
__device__ __forceinline__ void cp16(void* sdst, const void* gsrc) {
    unsigned s = (unsigned)__cvta_generic_to_shared(sdst);
    asm volatile("cp.async.cg.shared.global [%0], [%1], 16;\n" :: "r"(s), "l"(gsrc));
}
#define CP_COMMIT() asm volatile("cp.async.commit_group;\n")
#define CP_WAIT1()  asm volatile("cp.async.wait_group 1;\n")
#define CP_WAIT2()  asm volatile("cp.async.wait_group 2;\n")

// channel barrier primitives
__device__ __forceinline__ void ch_arrive(int ch, unsigned total, unsigned gen, int tid) {
    __syncthreads();
    if (tid == 0) {
        __threadfence();
        unsigned old = atomicAdd(&g_ccnt[ch], 1u);
        if (old == total - 1) {
            g_ccnt[ch] = 0;
            __threadfence();
            g_cgen[ch] = gen;
        }
    }
}
__device__ __forceinline__ void ch_wait(int ch, unsigned gen, int tid) {
    if (tid == 0) {
        while (g_cgen[ch] < gen) __nanosleep(32);
        __threadfence();
    }
    __syncthreads();
}
__device__ __forceinline__ void ch_wait2(int c0, int c1, unsigned gen, int tid) {
    if (tid == 0) {
        while (g_cgen[c0] < gen) __nanosleep(32);
        while (g_cgen[c1] < gen) __nanosleep(32);
        __threadfence();
    }
    __syncthreads();
}

// ---------------- init kernels ----------------
__global__ void k_round_all(const float* __restrict__ enc, const float* __restrict__ Ua,
                            const float* __restrict__ Wa, const float* __restrict__ Whh,
                            const float* __restrict__ Wih) {
    const int nEnc = Bsz * Ssz * Hsz / 4;
    const int nUa  = Hsz * Hsz / 4;
    const int nWhh = 3 * Hsz * Hsz / 4;
    const int nWih = 3 * Hsz * 2 * Hsz / 4;
    const int e0 = nEnc, e1 = e0 + nUa, e2 = e1 + nUa, e3 = e2 + nWhh, e4 = e3 + nWih;
    for (int i = blockIdx.x * blockDim.x + threadIdx.x; i < e4; i += gridDim.x * blockDim.x) {
        const float4* src; float4* dst;
        if (i < e0)      { src = (const float4*)enc + i;        dst = (float4*)g_enc32 + i; }
        else if (i < e1) { src = (const float4*)Ua + (i - e0);  dst = (float4*)g_Ua32 + (i - e0); }
        else if (i < e2) { src = (const float4*)Wa + (i - e1);  dst = (float4*)g_Wa32 + (i - e1); }
        else if (i < e3) { src = (const float4*)Whh + (i - e2); dst = (float4*)g_Whh32 + (i - e2); }
        else             { src = (const float4*)Wih + (i - e3); dst = (float4*)g_Wih32 + (i - e3); }
        float4 v = *src;
        v.x = rnd32(v.x); v.y = rnd32(v.y); v.z = rnd32(v.z); v.w = rnd32(v.w);
        *dst = v;
    }
}

__global__ void k_embed_init(const int* __restrict__ target, const float* __restrict__ emb,
                             const float* __restrict__ eh) {
    int bx = blockIdx.x;
    if (bx < Tsz * Bsz) {
        int t = bx / Bsz, b = bx % Bsz;
        int tok = (t == 0) ? 0 : target[b * Tsz + t - 1];
        const float4* src = (const float4*)(emb + (size_t)tok * Hsz);
        float4* dst = (float4*)(g_emb + ((size_t)t * Bsz + b) * Hsz);
        for (int j = threadIdx.x; j < Hsz / 4; j += blockDim.x) {
            float4 v = src[j];
            v.x = rnd32(v.x); v.y = rnd32(v.y); v.z = rnd32(v.z); v.w = rnd32(v.w);
            dst[j] = v;
        }
    } else {
        int i = (bx - Tsz * Bsz) * 256 + threadIdx.x;
        if (i < Bsz * Hsz) { g_h[i] = eh[i]; g_h32[i] = rnd32(eh[i]); }
    }
}

__global__ void k_wout_conv(const float* __restrict__ W) {
    int n4 = Vsz * Hsz / 4;
    for (int i = blockIdx.x * blockDim.x + threadIdx.x; i < n4; i += gridDim.x * blockDim.x) {
        float4 v = ((const float4*)W)[i];
        ((__nv_bfloat162*)g_wout)[2 * i]     = __floats2bfloat162_rn(v.x, v.y);
        ((__nv_bfloat162*)g_wout)[2 * i + 1] = __floats2bfloat162_rn(v.z, v.w);
    }
}

// ---------------- tf32 64x128 tile GEMM, cp.async 3-stage, BK=16 ----------------
__device__ __forceinline__ void gemm64x128(const float* __restrict__ A, int lda,
                                           const float* __restrict__ B, int ldb,
                                           float* __restrict__ C, int ldc,
                                           int kiters, float* sbuf) {
    float (*As)[64][20]  = (float(*)[64][20])sbuf;
    float (*Bs)[128][20] = (float(*)[128][20])(sbuf + 3 * 64 * 20);
    int tid = threadIdx.x;
    int ra = tid >> 2, ca = (tid & 3) << 2;
    int rb = tid >> 1, cb = (tid & 1) << 3;
    int warp = tid >> 5, wm = warp >> 2, wn = warp & 3;

    const float* Ap = A + (size_t)ra * lda + ca;
    const float* Bp = B + (size_t)rb * ldb + cb;

    wmma::fragment<wmma::accumulator, 16, 16, 8, float> acc[2][2];
#pragma unroll
    for (int i = 0; i < 2; i++)
#pragma unroll
        for (int j = 0; j < 2; j++) wmma::fill_fragment(acc[i][j], 0.f);

#pragma unroll
    for (int s = 0; s < 2; s++) {
        if (s < kiters) {
            cp16(&As[s][ra][ca], Ap + s * 16);
            cp16(&Bs[s][rb][cb], Bp + s * 16);
            cp16(&Bs[s][rb][cb + 4], Bp + s * 16 + 4);
        }
        CP_COMMIT();
    }

    int stg = 2;
    for (int it = 0; it < kiters; it++) {
        int cur = it % 3;
        CP_WAIT1();
        __syncthreads();
        if (it + 2 < kiters) {
            cp16(&As[stg][ra][ca], Ap + (it + 2) * 16);
            cp16(&Bs[stg][rb][cb], Bp + (it + 2) * 16);
            cp16(&Bs[stg][rb][cb + 4], Bp + (it + 2) * 16 + 4);
        }
        CP_COMMIT();
        stg++; if (stg == 3) stg = 0;
#pragma unroll
        for (int ks = 0; ks < 2; ks++) {
            wmma::fragment<wmma::matrix_a, 16, 16, 8, wmma::precision::tf32, wmma::row_major> af0, af1;
            wmma::fragment<wmma::matrix_b, 16, 16, 8, wmma::precision::tf32, wmma::col_major> bf0, bf1;
            wmma::load_matrix_sync(af0, &As[cur][wm * 32][ks * 8], 20);
            wmma::load_matrix_sync(af1, &As[cur][wm * 32 + 16][ks * 8], 20);
            wmma::load_matrix_sync(bf0, &Bs[cur][wn * 32][ks * 8], 20);
            wmma::load_matrix_sync(bf1, &Bs[cur][wn * 32 + 16][ks * 8], 20);
            wmma::mma_sync(acc[0][0], af0, bf0, acc[0][0]);
            wmma::mma_sync(acc[0][1], af0, bf1, acc[0][1]);
            wmma::mma_sync(acc[1][0], af1, bf0, acc[1][0]);
            wmma::mma_sync(acc[1][1], af1, bf1, acc[1][1]);
        }
    }
    __syncthreads();
#pragma unroll
    for (int i = 0; i < 2; i++)
#pragma unroll
        for (int j = 0; j < 2; j++)
            wmma::store_matrix_sync(C + (size_t)(wm * 32 + i * 16) * ldc + wn * 32 + j * 16,
                                    acc[i][j], ldc, wmma::mem_row_major);
}

// merged precompute: keysU (512 tiles) + giE (960 tiles)
__global__ __launch_bounds__(NTHR, 3) void k_gemm_pre() {
    __shared__ float sbuf[11520];
    int bx = blockIdx.x;
    if (bx < 512) {
        int nt = bx & 7, mt = bx >> 3;
        int m0 = mt * 64, n0 = nt * 128;
        gemm64x128(g_enc32 + (size_t)m0 * Hsz, Hsz, g_Ua32 + (size_t)n0 * Hsz, Hsz,
                   g_keysU + (size_t)m0 * Hsz + n0, Hsz, 64, sbuf);
    } else {
        int idx = bx - 512;
        int nt = idx % 24, t = idx / 24;
        int n0 = nt * 128;
        gemm64x128(g_emb + (size_t)t * Bsz * Hsz, Hsz,
                   g_Wih32 + (size_t)n0 * (2 * Hsz), 2 * Hsz,
                   g_giE + (size_t)t * Bsz * 3 * Hsz + n0, 3 * Hsz, 64, sbuf);
    }
}

// ---------------- persistent recurrence kernel ----------------
__global__ __launch_bounds__(NTHR, 1) void k_persist(
    const float* __restrict__ enc, const float* __restrict__ Va,
    const float* __restrict__ ba, const float* __restrict__ bu,
    const float* __restrict__ b_ih, const float* __restrict__ b_hh,
    float* __restrict__ out_attn, float* __restrict__ out_hid)
{
    __shared__ float sbuf[11520];
    __shared__ unsigned s_gen0;
    int tid = threadIdx.x;
    int bx = blockIdx.x;
    if (tid == 0) s_gen0 = *((volatile unsigned*)&g_bargen);
    __syncthreads();
    unsigned gen = s_gen0;

    auto gbar = [&]() {
        gen++;
        __syncthreads();
        if (tid == 0) {
            __threadfence();
            unsigned a = atomicAdd(&g_barcnt, 1u);
            if (a == NBLK - 1) {
                g_barcnt = 0;
                __threadfence();
                *((volatile unsigned*)&g_bargen) = gen;
            } else {
                while (*((volatile unsigned*)&g_bargen) != gen) __nanosleep(32);
                __threadfence();
            }
        }
        __syncthreads();
    };

    // pre-phase: fold attention biases into keysU; reset channels
    for (int i = bx * NTHR + tid; i < Bsz * Ssz * Hsz; i += NBLK * NTHR) {
        int n = i & (Hsz - 1);
        g_keysU[i] += ba[n] + bu[n];
    }
    gbar();
    if (bx == 0 && tid == 0) {
#pragma unroll
        for (int c = 0; c < 8; c++) { g_ccnt[c] = 0; g_cgen[c] = 0; }
    }
    gbar();

    // weighted score partition: blocks 0-39: 31 pairs, 40-99: 30, 100-147: 22 (gh blocks)
    int sc_start, sc_cnt;
    if (bx < 40)       { sc_start = bx * 31;                sc_cnt = 31; }
    else if (bx < 100) { sc_start = 1240 + (bx - 40) * 30;  sc_cnt = 30; }
    else               { sc_start = 3040 + (bx - 100) * 22; sc_cnt = 22; }

    for (int t = 0; t < Tsz; t++) {
        unsigned g = (unsigned)t + 1;

        // ---- q: blocks 0-31 (8 n-tiles x split-K4, K=256) ----
        if (bx < 32) {
            ch_wait(CH_H, (unsigned)t, tid);
            int jt = bx >> 2, kh = bx & 3, n0 = jt * 128;
            gemm64x128(g_h32 + kh * 256, Hsz,
                       g_Wa32 + (size_t)n0 * Hsz + kh * 256, Hsz,
                       g_q4[kh] + n0, Hsz, 16, sbuf);
            ch_arrive(CH_Q, 32, g, tid);
        }

        // ---- gh: blocks 100-147 (24 n-tiles x split-K2, K=512) ----
        if (bx >= 100) {
            ch_wait(CH_H, (unsigned)t, tid);
            int idx = bx - 100, jt = idx >> 1, kh = idx & 1, n0 = jt * 128;
            gemm64x128(g_h32 + kh * 512, Hsz,
                       g_Whh32 + (size_t)n0 * Hsz + kh * 512, Hsz,
                       g_gh2[kh] + n0, 3 * Hsz, 32, sbuf);
            ch_arrive(CH_GH, 48, g, tid);
        }

        // ---- B: scores on ALL 148 blocks, smem-cached q row per batch ----
        {
            ch_wait(CH_Q, g, tid);
            float* qs = sbuf;            // 1024
            float* va = sbuf + 1024;     // 1024
            int end = sc_start + sc_cnt;
            int b0 = sc_start >> 6, b1 = (end - 1) >> 6;
            int w = tid >> 5, lane = tid & 31;
            for (int b = b0; b <= b1; b++) {
                for (int j = tid; j < Hsz; j += NTHR) {
                    qs[j] = g_q4[0][b * Hsz + j] + g_q4[1][b * Hsz + j]
                          + g_q4[2][b * Hsz + j] + g_q4[3][b * Hsz + j];
                    va[j] = Va[j];
                }
                __syncthreads();
                int ps = sc_start > (b << 6) ? sc_start : (b << 6);
                int pe = end < ((b + 1) << 6) ? end : ((b + 1) << 6);
                for (int p = ps + w; p < pe; p += 8) {
                    const float* kp = g_keysU + (size_t)p * Hsz;
                    float acc = 0.f;
#pragma unroll 8
                    for (int jj = 0; jj < 32; jj++) {
                        int j = lane + jj * 32;
                        acc += va[j] * tanh_fast(qs[j] + kp[j]);
                    }
#pragma unroll
                    for (int o = 16; o > 0; o >>= 1) acc += __shfl_xor_sync(0xffffffffu, acc, o);
                    if (lane == 0) g_sc[p] = acc;
                }
                __syncthreads();
            }
            ch_arrive(CH_SC, NBLK, g, tid);
        }

        // ---- C: softmax + ctx, blocks 0-63 ----
        if (bx < 64) {
            ch_wait(CH_SC, g, tid);
            int b = bx;
            float* ws = sbuf;
            int w = tid >> 5, lane = tid & 31;
            if (w == 0) {
                float v0 = g_sc[b * 64 + lane], v1 = g_sc[b * 64 + 32 + lane];
                float m = fmaxf(v0, v1);
#pragma unroll
                for (int o = 16; o > 0; o >>= 1) m = fmaxf(m, __shfl_xor_sync(0xffffffffu, m, o));
                float e0 = __expf(v0 - m), e1 = __expf(v1 - m);
                float ssum = e0 + e1;
#pragma unroll
                for (int o = 16; o > 0; o >>= 1) ssum += __shfl_xor_sync(0xffffffffu, ssum, o);
                float inv = __fdividef(1.f, ssum);
                ws[lane] = e0 * inv;
                ws[lane + 32] = e1 * inv;
            }
            __syncthreads();
            if (tid < Ssz) out_attn[(size_t)b * Tsz * Ssz + t * Ssz + tid] = ws[tid];
            float c0 = 0.f, c1 = 0.f, c2 = 0.f, c3 = 0.f;
            const float* ep = enc + (size_t)b * Ssz * Hsz + tid;
#pragma unroll 4
            for (int s = 0; s < Ssz; s++) {
                float wv = ws[s];
                const float* row = ep + (size_t)s * Hsz;
                c0 += wv * row[0];
                c1 += wv * row[256];
                c2 += wv * row[512];
                c3 += wv * row[768];
            }
            g_ctx[b * Hsz + tid]       = rnd32(c0);
            g_ctx[b * Hsz + tid + 256] = rnd32(c1);
            g_ctx[b * Hsz + tid + 512] = rnd32(c2);
            g_ctx[b * Hsz + tid + 768] = rnd32(c3);
            ch_arrive(CH_CTX, 64, g, tid);
        }

        // ---- D: gi_ctx = ctx @ W_ih[:, H:2H]^T, blocks 0-95 ----
        if (bx < 96) {
            ch_wait(CH_CTX, g, tid);
            int jt = bx >> 2, kh = bx & 3, n0 = jt * 128;
            gemm64x128(g_ctx + kh * 256, Hsz,
                       g_Wih32 + (size_t)n0 * (2 * Hsz) + Hsz + kh * 256, 2 * Hsz,
                       g_gc4[kh] + n0, 3 * Hsz, 16, sbuf);
            ch_arrive(CH_D, 96, g, tid);
        }

        // ---- E: gates + h update, all blocks ----
        ch_wait2(CH_D, CH_GH, g, tid);
        {
            const float* giE = g_giE + (size_t)t * Bsz * 3 * Hsz;
            for (int i = bx * NTHR + tid; i < Bsz * Hsz; i += NBLK * NTHR) {
                int b = i >> 10, j = i & (Hsz - 1);
                size_t base3 = (size_t)b * 3 * Hsz;
                float ir = giE[base3 + j] + b_ih[j];
                float iz = giE[base3 + Hsz + j] + b_ih[Hsz + j];
                float in = giE[base3 + 2 * Hsz + j] + b_ih[2 * Hsz + j];
#pragma unroll
                for (int kh = 0; kh < 4; kh++) {
                    ir += g_gc4[kh][base3 + j];
                    iz += g_gc4[kh][base3 + Hsz + j];
                    in += g_gc4[kh][base3 + 2 * Hsz + j];
                }
                float hr = b_hh[j]           + g_gh2[0][base3 + j]           + g_gh2[1][base3 + j];
                float hz = b_hh[Hsz + j]     + g_gh2[0][base3 + Hsz + j]     + g_gh2[1][base3 + Hsz + j];
                float hn = b_hh[2 * Hsz + j] + g_gh2[0][base3 + 2 * Hsz + j] + g_gh2[1][base3 + 2 * Hsz + j];
                float rr = fsigmoid(ir + hr);
                float zz = fsigmoid(iz + hz);
                float nn = ftanh(in + rr * hn);
                float hp = g_h[i];
                float hnew = (1.f - zz) * nn + zz * hp;
                g_h[i] = hnew;
                g_h32[i] = rnd32(hnew);
                g_hall[((size_t)t * Bsz + b) * Hsz + j] = __float2bfloat16(hnew);
            }
        }
        ch_arrive(CH_H, NBLK, g, tid);
    }

    for (int i = bx * NTHR + tid; i < Bsz * Hsz; i += NBLK * NTHR)
        out_hid[i] = g_h[i];
}

// ---------------- output projection: logits = Hall @ Wout^T + b_out ----------------
#define OUT_STAGE_B 10240
__global__ __launch_bounds__(256, 2) void k_gemm_out(const float* __restrict__ b_out,
                                                     float* __restrict__ out) {
    extern __shared__ char dyn[];
    char* sA = dyn;
    char* sB = dyn + 4 * OUT_STAGE_B;
    const int K = Hsz;
    int m0 = blockIdx.y * 128, n0 = blockIdx.x * 128;
    int tid = threadIdx.x;
    int warp = tid >> 5, lane = tid & 31;
    int wm = warp >> 2, wn = warp & 3;

    const char* Ag = (const char*)(g_hall + (size_t)m0 * K);
    const char* Bg = (const char*)(g_wout + (size_t)n0 * K);

    int c0 = tid * 2;
    int rowA0 = c0 >> 2, off0 = (c0 & 3) * 16;
    int rowA1 = (c0 + 1) >> 2, off1 = ((c0 + 1) & 3) * 16;

    auto load_stage = [&](int kt, int s) {
        char* dA = sA + s * OUT_STAGE_B;
        char* dB = sB + s * OUT_STAGE_B;
        const char* a0 = Ag + (size_t)rowA0 * (K * 2) + kt * 64 + off0;
        const char* a1 = Ag + (size_t)rowA1 * (K * 2) + kt * 64 + off1;
        const char* b0 = Bg + (size_t)rowA0 * (K * 2) + kt * 64 + off0;
        const char* b1 = Bg + (size_t)rowA1 * (K * 2) + kt * 64 + off1;
        cp16(dA + rowA0 * 80 + off0, a0);
        cp16(dA + rowA1 * 80 + off1, a1);
        cp16(dB + rowA0 * 80 + off0, b0);
        cp16(dB + rowA1 * 80 + off1, b1);
        CP_COMMIT();
    };

    wmma::fragment<wmma::accumulator, 16, 16, 16, float> acc[4][2];
#pragma unroll
    for (int i = 0; i < 4; i++)
#pragma unroll
        for (int j = 0; j < 2; j++) wmma::fill_fragment(acc[i][j], 0.f);

    load_stage(0, 0);
    load_stage(1, 1);
    load_stage(2, 2);

    const int NKT = K / 32;
    for (int kt = 0; kt < NKT; kt++) {
        int cur = kt & 3;
        CP_WAIT2();
        __syncthreads();
        if (kt + 3 < NKT) load_stage(kt + 3, (kt + 3) & 3);
        else CP_COMMIT();
        const __nv_bfloat16* As = (const __nv_bfloat16*)(sA + cur * OUT_STAGE_B);
        const __nv_bfloat16* Bs = (const __nv_bfloat16*)(sB + cur * OUT_STAGE_B);
#pragma unroll
        for (int ks = 0; ks < 2; ks++) {
            wmma::fragment<wmma::matrix_a, 16, 16, 16, __nv_bfloat16, wmma::row_major> af[4];
            wmma::fragment<wmma::matrix_b, 16, 16, 16, __nv_bfloat16, wmma::col_major> bf[2];
#pragma unroll
            for (int i = 0; i < 4; i++)
                wmma::load_matrix_sync(af[i], As + (wm * 64 + i * 16) * 40 + ks * 16, 40);
#pragma unroll
            for (int j = 0; j < 2; j++)
                wmma::load_matrix_sync(bf[j], Bs + (wn * 32 + j * 16) * 40 + ks * 16, 40);
#pragma unroll
            for (int i = 0; i < 4; i++)
#pragma unroll
                for (int j = 0; j < 2; j++)
                    wmma::mma_sync(acc[i][j], af[i], bf[j], acc[i][j]);
        }
    }
    __syncthreads();

    float* stage = (float*)dyn;
    float* sp = stage + warp * 320;
#pragma unroll
    for (int i = 0; i < 4; i++) {
#pragma unroll
        for (int j = 0; j < 2; j++) {
            wmma::store_matrix_sync(sp, acc[i][j], 20, wmma::mem_row_major);
            __syncwarp();
            int gr0 = m0 + wm * 64 + i * 16;
            int gc0 = n0 + wn * 32 + j * 16;
            for (int e = lane; e < 256; e += 32) {
                int r = e >> 4, cc = e & 15;
                int gr = gr0 + r, gc = gc0 + cc;
                int bb = gr & 63, tt = gr >> 6;
                out[(size_t)(bb * Tsz + tt) * Vsz + gc] = sp[r * 20 + cc] + b_out[gc];
            }
            __syncwarp();
        }
    }
}

// ---------------- in-place log_softmax (float4) ----------------
__global__ __launch_bounds__(256) void k_logsoftmax(float* __restrict__ out) {
    int row = blockIdx.x;
    float4* p4 = (float4*)(out + (size_t)row * Vsz);
    const int N4 = Vsz / 4;
    int tid = threadIdx.x;
    float m = -1e30f, s = 0.f;
    for (int j = tid; j < N4; j += 256) {
        float4 v = p4[j];
        float vm = fmaxf(fmaxf(v.x, v.y), fmaxf(v.z, v.w));
        if (vm > m) { s = s * __expf(m - vm); m = vm; }
        s += __expf(v.x - m) + __expf(v.y - m) + __expf(v.z - m) + __expf(v.w - m);
    }
    __shared__ float sm[256], ss[256];
    sm[tid] = m; ss[tid] = s;
    __syncthreads();
    for (int o = 128; o > 0; o >>= 1) {
        if (tid < o) {
            float m2 = sm[tid + o], s2 = ss[tid + o];
            float mm = fmaxf(sm[tid], m2);
            ss[tid] = ss[tid] * __expf(sm[tid] - mm) + s2 * __expf(m2 - mm);
            sm[tid] = mm;
        }
        __syncthreads();
    }
    float L = sm[0] + logf(ss[0]);
    for (int j = tid; j < N4; j += 256) {
        float4 v = p4[j];
        v.x -= L; v.y -= L; v.z -= L; v.w -= L;
        p4[j] = v;
    }
}

// ---------------- launch ----------------
extern "C" void kernel_launch(void* const* d_in, const int* in_sizes, int n_in,
                              void* d_out, int out_size) {
    const float* enc_out = (const float*)d_in[0];
    const float* enc_hid = (const float*)d_in[1];
    const int*   target  = (const int*)d_in[2];
    const float* embedding = (const float*)d_in[3];
    const float* Wa  = (const float*)d_in[4];
    const float* ba  = (const float*)d_in[5];
    const float* Ua  = (const float*)d_in[6];
    const float* bu  = (const float*)d_in[7];
    const float* Va  = (const float*)d_in[8];
    // d_in[9] = bv : softmax shift-invariant, unused
    const float* W_ih = (const float*)d_in[10];
    const float* W_hh = (const float*)d_in[11];
    const float* b_ih = (const float*)d_in[12];
    const float* b_hh = (const float*)d_in[13];
    const float* W_out = (const float*)d_in[14];
    const float* b_out = (const float*)d_in[15];

    float* out = (float*)d_out;
    float* out_dec  = out;                                        // [B,T,V]
    float* out_hid  = out + (size_t)Bsz * Tsz * Vsz;              // [1,B,H]
    float* out_attn = out_hid + (size_t)Bsz * Hsz;                // [B,T,S]

    cudaFuncSetAttribute(k_gemm_out, cudaFuncAttributeMaxDynamicSharedMemorySize,
                         8 * OUT_STAGE_B);

    // init
    k_round_all<<<1024, 256>>>(enc_out, Ua, Wa, W_hh, W_ih);
    k_embed_init<<<Tsz * Bsz + 256, 256>>>(target, embedding, enc_hid);
    k_wout_conv<<<2048, 256>>>(W_out);
    k_gemm_pre<<<512 + 960, NTHR>>>();

    // full recurrence in one launch
    k_persist<<<NBLK, NTHR>>>(enc_out, Va, ba, bu, b_ih, b_hh, out_attn, out_hid);

    // output projection + log_softmax
    {
        dim3 grid(Vsz / 128, (Tsz * Bsz) / 128);  // 250 x 20
        k_gemm_out<<<grid, 256, 8 * OUT_STAGE_B>>>(b_out, out_dec);
    }
    k_logsoftmax<<<Tsz * Bsz, 256>>>(out_dec);
}

// round 13
// speedup vs baseline: 1.0788x; 1.0788x over previous
#include <cuda_runtime.h>
#include <cuda_bf16.h>
#include <mma.h>
#include <cstdint>

using namespace nvcuda;

#define Bsz 64
#define Ssz 64
#define Hsz 1024
#define Vsz 32000
#define Tsz 40
#define NBLK 148
#define NTHR 256

// ---------------- scratch ----------------
__device__ float g_keysU[Bsz * Ssz * Hsz];          // 16 MB (bias added in persist)
__device__ float g_emb[Tsz * Bsz * Hsz];            // 10 MB [t][b][h] (tf32-rounded)
__device__ float g_h[Bsz * Hsz];                    // exact fp32 hidden
__device__ float g_h32[Bsz * Hsz];                  // tf32-rounded copy for GEMMs
__device__ float g_q4[4][Bsz * Hsz];                // q split-K parts
__device__ float g_gh2[2][Bsz * 3 * Hsz];           // gh split-K parts (K=512 x2)
__device__ float g_gc4[4][Bsz * 3 * Hsz];           // gi ctx-half split-K parts
__device__ float g_giE[(size_t)Tsz * Bsz * 3 * Hsz];// 31.5 MB
__device__ float g_ctx[Bsz * Hsz];                  // tf32-rounded at store
__device__ __nv_bfloat16 g_hall[Tsz * Bsz * Hsz];   // 5 MB
__device__ __nv_bfloat16 g_wout[Vsz * Hsz];         // 65 MB
__device__ float2 g_part[(size_t)Tsz * Bsz * 250];  // 5.1 MB log-softmax partials
// tf32-RN pre-rounded operand copies
__device__ float g_enc32[Bsz * Ssz * Hsz];          // 16 MB
__device__ float g_Ua32[Hsz * Hsz];
__device__ float g_Wa32[Hsz * Hsz];
__device__ float g_Whh32[3 * Hsz * Hsz];
__device__ float g_Wih32[3 * Hsz * 2 * Hsz];
__device__ unsigned g_barcnt = 0;
__device__ unsigned g_bargen = 0;
// dependency channels
__device__ unsigned g_ccnt[8];
__device__ volatile unsigned g_cgen[8];
#define CH_Q 0
#define CH_CTX 1
#define CH_D 2
#define CH_GH 3
#define CH_H 4

// fast activations
__device__ __forceinline__ float tanh_fast(float x) {
    float y; asm("tanh.approx.f32 %0, %1;" : "=f"(y) : "f"(x)); return y;
}
__device__ __forceinline__ float ftanh(float x) {
    float e = __expf(2.f * x);
    return 1.f - __fdividef(2.f, e + 1.f);
}
__device__ __forceinline__ float fsigmoid(float x) {
    return __fdividef(1.f, 1.f + __expf(-x));
}
__device__ __forceinline__ float rnd32(float x) {
    float y; asm("cvt.rna.tf32.f32 %0, %1;" : "=f"(y) : "f"(x)); return y;
}

// cp.async helpers
__device__ __forceinline__ void cp16(void* sdst, const void* gsrc) {
    unsigned s = (unsigned)__cvta_generic_to_shared(sdst);
    asm volatile("cp.async.cg.shared.global [%0], [%1], 16;\n" :: "r"(s), "l"(gsrc));
}
#define CP_COMMIT() asm volatile("cp.async.commit_group;\n")
#define CP_WAIT1()  asm volatile("cp.async.wait_group 1;\n")
#define CP_WAIT2()  asm volatile("cp.async.wait_group 2;\n")

// channel barrier primitives
__device__ __forceinline__ void ch_arrive(int ch, unsigned total, unsigned gen, int tid) {
    __syncthreads();
    if (tid == 0) {
        __threadfence();
        unsigned old = atomicAdd(&g_ccnt[ch], 1u);
        if (old == total - 1) {
            g_ccnt[ch] = 0;
            __threadfence();
            g_cgen[ch] = gen;
        }
    }
}
__device__ __forceinline__ void ch_wait(int ch, unsigned gen, int tid) {
    if (tid == 0) {
        while (g_cgen[ch] < gen) __nanosleep(32);
        __threadfence();
    }
    __syncthreads();
}
__device__ __forceinline__ void ch_wait2(int c0, int c1, unsigned gen, int tid) {
    if (tid == 0) {
        while (g_cgen[c0] < gen) __nanosleep(32);
        while (g_cgen[c1] < gen) __nanosleep(32);
        __threadfence();
    }
    __syncthreads();
}

// ---------------- init kernels ----------------
__global__ void k_round_all(const float* __restrict__ enc, const float* __restrict__ Ua,
                            const float* __restrict__ Wa, const float* __restrict__ Whh,
                            const float* __restrict__ Wih) {
    const int nEnc = Bsz * Ssz * Hsz / 4;
    const int nUa  = Hsz * Hsz / 4;
    const int nWhh = 3 * Hsz * Hsz / 4;
    const int nWih = 3 * Hsz * 2 * Hsz / 4;
    const int e0 = nEnc, e1 = e0 + nUa, e2 = e1 + nUa, e3 = e2 + nWhh, e4 = e3 + nWih;
    for (int i = blockIdx.x * blockDim.x + threadIdx.x; i < e4; i += gridDim.x * blockDim.x) {
        const float4* src; float4* dst;
        if (i < e0)      { src = (const float4*)enc + i;        dst = (float4*)g_enc32 + i; }
        else if (i < e1) { src = (const float4*)Ua + (i - e0);  dst = (float4*)g_Ua32 + (i - e0); }
        else if (i < e2) { src = (const float4*)Wa + (i - e1);  dst = (float4*)g_Wa32 + (i - e1); }
        else if (i < e3) { src = (const float4*)Whh + (i - e2); dst = (float4*)g_Whh32 + (i - e2); }
        else             { src = (const float4*)Wih + (i - e3); dst = (float4*)g_Wih32 + (i - e3); }
        float4 v = *src;
        v.x = rnd32(v.x); v.y = rnd32(v.y); v.z = rnd32(v.z); v.w = rnd32(v.w);
        *dst = v;
    }
}

__global__ void k_embed_init(const int* __restrict__ target, const float* __restrict__ emb,
                             const float* __restrict__ eh) {
    int bx = blockIdx.x;
    if (bx < Tsz * Bsz) {
        int t = bx / Bsz, b = bx % Bsz;
        int tok = (t == 0) ? 0 : target[b * Tsz + t - 1];
        const float4* src = (const float4*)(emb + (size_t)tok * Hsz);
        float4* dst = (float4*)(g_emb + ((size_t)t * Bsz + b) * Hsz);
        for (int j = threadIdx.x; j < Hsz / 4; j += blockDim.x) {
            float4 v = src[j];
            v.x = rnd32(v.x); v.y = rnd32(v.y); v.z = rnd32(v.z); v.w = rnd32(v.w);
            dst[j] = v;
        }
    } else {
        int i = (bx - Tsz * Bsz) * 256 + threadIdx.x;
        if (i < Bsz * Hsz) { g_h[i] = eh[i]; g_h32[i] = rnd32(eh[i]); }
    }
}

__global__ void k_wout_conv(const float* __restrict__ W) {
    int n4 = Vsz * Hsz / 4;
    for (int i = blockIdx.x * blockDim.x + threadIdx.x; i < n4; i += gridDim.x * blockDim.x) {
        float4 v = ((const float4*)W)[i];
        ((__nv_bfloat162*)g_wout)[2 * i]     = __floats2bfloat162_rn(v.x, v.y);
        ((__nv_bfloat162*)g_wout)[2 * i + 1] = __floats2bfloat162_rn(v.z, v.w);
    }
}

// ---------------- tf32 64x128 tile GEMM, cp.async 3-stage, BK=16 ----------------
__device__ __forceinline__ void gemm64x128(const float* __restrict__ A, int lda,
                                           const float* __restrict__ B, int ldb,
                                           float* __restrict__ C, int ldc,
                                           int kiters, float* sbuf) {
    float (*As)[64][20]  = (float(*)[64][20])sbuf;
    float (*Bs)[128][20] = (float(*)[128][20])(sbuf + 3 * 64 * 20);
    int tid = threadIdx.x;
    int ra = tid >> 2, ca = (tid & 3) << 2;
    int rb = tid >> 1, cb = (tid & 1) << 3;
    int warp = tid >> 5, wm = warp >> 2, wn = warp & 3;

    const float* Ap = A + (size_t)ra * lda + ca;
    const float* Bp = B + (size_t)rb * ldb + cb;

    wmma::fragment<wmma::accumulator, 16, 16, 8, float> acc[2][2];
#pragma unroll
    for (int i = 0; i < 2; i++)
#pragma unroll
        for (int j = 0; j < 2; j++) wmma::fill_fragment(acc[i][j], 0.f);

#pragma unroll
    for (int s = 0; s < 2; s++) {
        if (s < kiters) {
            cp16(&As[s][ra][ca], Ap + s * 16);
            cp16(&Bs[s][rb][cb], Bp + s * 16);
            cp16(&Bs[s][rb][cb + 4], Bp + s * 16 + 4);
        }
        CP_COMMIT();
    }

    int stg = 2;
    for (int it = 0; it < kiters; it++) {
        int cur = it % 3;
        CP_WAIT1();
        __syncthreads();
        if (it + 2 < kiters) {
            cp16(&As[stg][ra][ca], Ap + (it + 2) * 16);
            cp16(&Bs[stg][rb][cb], Bp + (it + 2) * 16);
            cp16(&Bs[stg][rb][cb + 4], Bp + (it + 2) * 16 + 4);
        }
        CP_COMMIT();
        stg++; if (stg == 3) stg = 0;
#pragma unroll
        for (int ks = 0; ks < 2; ks++) {
            wmma::fragment<wmma::matrix_a, 16, 16, 8, wmma::precision::tf32, wmma::row_major> af0, af1;
            wmma::fragment<wmma::matrix_b, 16, 16, 8, wmma::precision::tf32, wmma::col_major> bf0, bf1;
            wmma::load_matrix_sync(af0, &As[cur][wm * 32][ks * 8], 20);
            wmma::load_matrix_sync(af1, &As[cur][wm * 32 + 16][ks * 8], 20);
            wmma::load_matrix_sync(bf0, &Bs[cur][wn * 32][ks * 8], 20);
            wmma::load_matrix_sync(bf1, &Bs[cur][wn * 32 + 16][ks * 8], 20);
            wmma::mma_sync(acc[0][0], af0, bf0, acc[0][0]);
            wmma::mma_sync(acc[0][1], af0, bf1, acc[0][1]);
            wmma::mma_sync(acc[1][0], af1, bf0, acc[1][0]);
            wmma::mma_sync(acc[1][1], af1, bf1, acc[1][1]);
        }
    }
    __syncthreads();
#pragma unroll
    for (int i = 0; i < 2; i++)
#pragma unroll
        for (int j = 0; j < 2; j++)
            wmma::store_matrix_sync(C + (size_t)(wm * 32 + i * 16) * ldc + wn * 32 + j * 16,
                                    acc[i][j], ldc, wmma::mem_row_major);
}

// merged precompute: keysU (512 tiles) + giE (960 tiles)
__global__ __launch_bounds__(NTHR, 3) void k_gemm_pre() {
    __shared__ float sbuf[11520];
    int bx = blockIdx.x;
    if (bx < 512) {
        int nt = bx & 7, mt = bx >> 3;
        int m0 = mt * 64, n0 = nt * 128;
        gemm64x128(g_enc32 + (size_t)m0 * Hsz, Hsz, g_Ua32 + (size_t)n0 * Hsz, Hsz,
                   g_keysU + (size_t)m0 * Hsz + n0, Hsz, 64, sbuf);
    } else {
        int idx = bx - 512;
        int nt = idx % 24, t = idx / 24;
        int n0 = nt * 128;
        gemm64x128(g_emb + (size_t)t * Bsz * Hsz, Hsz,
                   g_Wih32 + (size_t)n0 * (2 * Hsz), 2 * Hsz,
                   g_giE + (size_t)t * Bsz * 3 * Hsz + n0, 3 * Hsz, 64, sbuf);
    }
}

// ---------------- persistent recurrence kernel (3319us R9 structure) ----------------
__global__ __launch_bounds__(NTHR, 1) void k_persist(
    const float* __restrict__ enc, const float* __restrict__ Va,
    const float* __restrict__ ba, const float* __restrict__ bu,
    const float* __restrict__ b_ih, const float* __restrict__ b_hh,
    float* __restrict__ out_attn, float* __restrict__ out_hid)
{
    __shared__ float sbuf[11520];
    __shared__ unsigned s_gen0;
    int tid = threadIdx.x;
    int bx = blockIdx.x;
    if (tid == 0) s_gen0 = *((volatile unsigned*)&g_bargen);
    __syncthreads();
    unsigned gen = s_gen0;

    auto gbar = [&]() {
        gen++;
        __syncthreads();
        if (tid == 0) {
            __threadfence();
            unsigned a = atomicAdd(&g_barcnt, 1u);
            if (a == NBLK - 1) {
                g_barcnt = 0;
                __threadfence();
                *((volatile unsigned*)&g_bargen) = gen;
            } else {
                while (*((volatile unsigned*)&g_bargen) != gen) __nanosleep(32);
                __threadfence();
            }
        }
        __syncthreads();
    };

    // pre-phase: fold attention biases into keysU; reset channels
    for (int i = bx * NTHR + tid; i < Bsz * Ssz * Hsz; i += NBLK * NTHR) {
        int n = i & (Hsz - 1);
        g_keysU[i] += ba[n] + bu[n];
    }
    gbar();
    if (bx == 0 && tid == 0) {
#pragma unroll
        for (int c = 0; c < 8; c++) { g_ccnt[c] = 0; g_cgen[c] = 0; }
    }
    gbar();

    for (int t = 0; t < Tsz; t++) {
        unsigned g = (unsigned)t + 1;

        // ---- q: blocks 0-31 (8 n-tiles x split-K4, K=256) ----
        if (bx < 32) {
            ch_wait(CH_H, (unsigned)t, tid);
            int jt = bx >> 2, kh = bx & 3, n0 = jt * 128;
            gemm64x128(g_h32 + kh * 256, Hsz,
                       g_Wa32 + (size_t)n0 * Hsz + kh * 256, Hsz,
                       g_q4[kh] + n0, Hsz, 16, sbuf);
            ch_arrive(CH_Q, 32, g, tid);
        }

        // ---- gh: blocks 100-147 (24 n-tiles x split-K2, K=512), overlaps BC/D ----
        if (bx >= 100) {
            ch_wait(CH_H, (unsigned)t, tid);
            int idx = bx - 100, jt = idx >> 1, kh = idx & 1, n0 = jt * 128;
            gemm64x128(g_h32 + kh * 512, Hsz,
                       g_Whh32 + (size_t)n0 * Hsz + kh * 512, Hsz,
                       g_gh2[kh] + n0, 3 * Hsz, 32, sbuf);
            ch_arrive(CH_GH, 48, g, tid);
        }

        // ---- BC: scores + softmax + ctx, blocks 0-63 (smem-cached q row) ----
        if (bx < 64) {
            ch_wait(CH_Q, g, tid);
            int b = bx;
            float* qs = sbuf;
            float* va = sbuf + 1024;
            float* sc = sbuf + 2048;
            float* ws = sbuf + 2112;
            for (int j = tid; j < Hsz; j += NTHR) {
                qs[j] = g_q4[0][b * Hsz + j] + g_q4[1][b * Hsz + j]
                      + g_q4[2][b * Hsz + j] + g_q4[3][b * Hsz + j];
                va[j] = Va[j];
            }
            __syncthreads();
            int w = tid >> 5, lane = tid & 31;
#pragma unroll
            for (int si = 0; si < 8; si++) {
                int s = w * 8 + si;
                const float* kp = g_keysU + (size_t)(b * Ssz + s) * Hsz;
                float acc = 0.f;
#pragma unroll 8
                for (int jj = 0; jj < 32; jj++) {
                    int j = lane + jj * 32;
                    acc += va[j] * tanh_fast(qs[j] + kp[j]);
                }
#pragma unroll
                for (int o = 16; o > 0; o >>= 1) acc += __shfl_xor_sync(0xffffffffu, acc, o);
                if (lane == 0) sc[s] = acc;
            }
            __syncthreads();
            if (w == 0) {
                float v0 = sc[lane], v1 = sc[lane + 32];
                float m = fmaxf(v0, v1);
#pragma unroll
                for (int o = 16; o > 0; o >>= 1) m = fmaxf(m, __shfl_xor_sync(0xffffffffu, m, o));
                float e0 = __expf(v0 - m), e1 = __expf(v1 - m);
                float ssum = e0 + e1;
#pragma unroll
                for (int o = 16; o > 0; o >>= 1) ssum += __shfl_xor_sync(0xffffffffu, ssum, o);
                float inv = __fdividef(1.f, ssum);
                ws[lane] = e0 * inv;
                ws[lane + 32] = e1 * inv;
            }
            __syncthreads();
            if (tid < Ssz) out_attn[(size_t)b * Tsz * Ssz + t * Ssz + tid] = ws[tid];
            float c0 = 0.f, c1 = 0.f, c2 = 0.f, c3 = 0.f;
            const float* ep = enc + (size_t)b * Ssz * Hsz + tid;
#pragma unroll 4
            for (int s = 0; s < Ssz; s++) {
                float wv = ws[s];
                const float* row = ep + (size_t)s * Hsz;
                c0 += wv * row[0];
                c1 += wv * row[256];
                c2 += wv * row[512];
                c3 += wv * row[768];
            }
            g_ctx[b * Hsz + tid]       = rnd32(c0);
            g_ctx[b * Hsz + tid + 256] = rnd32(c1);
            g_ctx[b * Hsz + tid + 512] = rnd32(c2);
            g_ctx[b * Hsz + tid + 768] = rnd32(c3);
            ch_arrive(CH_CTX, 64, g, tid);
        }

        // ---- D: gi_ctx = ctx @ W_ih[:, H:2H]^T, blocks 0-95 (24 n-tiles x split-K4) ----
        if (bx < 96) {
            ch_wait(CH_CTX, g, tid);
            int jt = bx >> 2, kh = bx & 3, n0 = jt * 128;
            gemm64x128(g_ctx + kh * 256, Hsz,
                       g_Wih32 + (size_t)n0 * (2 * Hsz) + Hsz + kh * 256, 2 * Hsz,
                       g_gc4[kh] + n0, 3 * Hsz, 16, sbuf);
            ch_arrive(CH_D, 96, g, tid);
        }

        // ---- E: gates + h update, all blocks ----
        ch_wait2(CH_D, CH_GH, g, tid);
        {
            const float* giE = g_giE + (size_t)t * Bsz * 3 * Hsz;
            for (int i = bx * NTHR + tid; i < Bsz * Hsz; i += NBLK * NTHR) {
                int b = i >> 10, j = i & (Hsz - 1);
                size_t base3 = (size_t)b * 3 * Hsz;
                float ir = giE[base3 + j] + b_ih[j];
                float iz = giE[base3 + Hsz + j] + b_ih[Hsz + j];
                float in = giE[base3 + 2 * Hsz + j] + b_ih[2 * Hsz + j];
#pragma unroll
                for (int kh = 0; kh < 4; kh++) {
                    ir += g_gc4[kh][base3 + j];
                    iz += g_gc4[kh][base3 + Hsz + j];
                    in += g_gc4[kh][base3 + 2 * Hsz + j];
                }
                float hr = b_hh[j]           + g_gh2[0][base3 + j]           + g_gh2[1][base3 + j];
                float hz = b_hh[Hsz + j]     + g_gh2[0][base3 + Hsz + j]     + g_gh2[1][base3 + Hsz + j];
                float hn = b_hh[2 * Hsz + j] + g_gh2[0][base3 + 2 * Hsz + j] + g_gh2[1][base3 + 2 * Hsz + j];
                float rr = fsigmoid(ir + hr);
                float zz = fsigmoid(iz + hz);
                float nn = ftanh(in + rr * hn);
                float hp = g_h[i];
                float hnew = (1.f - zz) * nn + zz * hp;
                g_h[i] = hnew;
                g_h32[i] = rnd32(hnew);
                g_hall[((size_t)t * Bsz + b) * Hsz + j] = __float2bfloat16(hnew);
            }
        }
        ch_arrive(CH_H, NBLK, g, tid);
    }

    for (int i = bx * NTHR + tid; i < Bsz * Hsz; i += NBLK * NTHR)
        out_hid[i] = g_h[i];
}

// ---------------- output projection + fused log-softmax partials ----------------
#define OUT_STAGE_B 10240
__global__ __launch_bounds__(256, 2) void k_gemm_out(const float* __restrict__ b_out,
                                                     float* __restrict__ out) {
    extern __shared__ char dyn[];
    char* sA = dyn;
    char* sB = dyn + 4 * OUT_STAGE_B;
    const int K = Hsz;
    int m0 = blockIdx.y * 128, n0 = blockIdx.x * 128;
    int tid = threadIdx.x;
    int warp = tid >> 5, lane = tid & 31;
    int wm = warp >> 2, wn = warp & 3;

    const char* Ag = (const char*)(g_hall + (size_t)m0 * K);
    const char* Bg = (const char*)(g_wout + (size_t)n0 * K);

    int c0 = tid * 2;
    int rowA0 = c0 >> 2, off0 = (c0 & 3) * 16;
    int rowA1 = (c0 + 1) >> 2, off1 = ((c0 + 1) & 3) * 16;

    auto load_stage = [&](int kt, int s) {
        char* dA = sA + s * OUT_STAGE_B;
        char* dB = sB + s * OUT_STAGE_B;
        const char* a0 = Ag + (size_t)rowA0 * (K * 2) + kt * 64 + off0;
        const char* a1 = Ag + (size_t)rowA1 * (K * 2) + kt * 64 + off1;
        const char* b0 = Bg + (size_t)rowA0 * (K * 2) + kt * 64 + off0;
        const char* b1 = Bg + (size_t)rowA1 * (K * 2) + kt * 64 + off1;
        cp16(dA + rowA0 * 80 + off0, a0);
        cp16(dA + rowA1 * 80 + off1, a1);
        cp16(dB + rowA0 * 80 + off0, b0);
        cp16(dB + rowA1 * 80 + off1, b1);
        CP_COMMIT();
    };

    wmma::fragment<wmma::accumulator, 16, 16, 16, float> acc[4][2];
#pragma unroll
    for (int i = 0; i < 4; i++)
#pragma unroll
        for (int j = 0; j < 2; j++) wmma::fill_fragment(acc[i][j], 0.f);

    load_stage(0, 0);
    load_stage(1, 1);
    load_stage(2, 2);

    const int NKT = K / 32;
    for (int kt = 0; kt < NKT; kt++) {
        int cur = kt & 3;
        CP_WAIT2();
        __syncthreads();
        if (kt + 3 < NKT) load_stage(kt + 3, (kt + 3) & 3);
        else CP_COMMIT();
        const __nv_bfloat16* As = (const __nv_bfloat16*)(sA + cur * OUT_STAGE_B);
        const __nv_bfloat16* Bs = (const __nv_bfloat16*)(sB + cur * OUT_STAGE_B);
#pragma unroll
        for (int ks = 0; ks < 2; ks++) {
            wmma::fragment<wmma::matrix_a, 16, 16, 16, __nv_bfloat16, wmma::row_major> af[4];
            wmma::fragment<wmma::matrix_b, 16, 16, 16, __nv_bfloat16, wmma::col_major> bf[2];
#pragma unroll
            for (int i = 0; i < 4; i++)
                wmma::load_matrix_sync(af[i], As + (wm * 64 + i * 16) * 40 + ks * 16, 40);
#pragma unroll
            for (int j = 0; j < 2; j++)
                wmma::load_matrix_sync(bf[j], Bs + (wn * 32 + j * 16) * 40 + ks * 16, 40);
#pragma unroll
            for (int i = 0; i < 4; i++)
#pragma unroll
                for (int j = 0; j < 2; j++)
                    wmma::mma_sync(acc[i][j], af[i], bf[j], acc[i][j]);
        }
    }
    __syncthreads();

    // epilogue: write logits + per-row online (max, sumexp) partials
    float* stage = (float*)dyn;
    float* sp = stage + warp * 320;                 // 16x20 per warp
    float* srow = (float*)(dyn + 12288);            // [128 rows][4 wn][m,s] = 4 KB
#pragma unroll
    for (int i = 0; i < 4; i++) {
        float rm = -1e30f, rs = 0.f;                // lane<16 stats for one row, 32 cols
#pragma unroll
        for (int j = 0; j < 2; j++) {
            wmma::store_matrix_sync(sp, acc[i][j], 20, wmma::mem_row_major);
            __syncwarp();
            int gr0 = m0 + wm * 64 + i * 16;
            int gc0 = n0 + wn * 32 + j * 16;
            for (int e = lane; e < 256; e += 32) {
                int r = e >> 4, cc = e & 15;
                int gr = gr0 + r, gc = gc0 + cc;
                int bb = gr & 63, tt = gr >> 6;
                float val = sp[r * 20 + cc] + b_out[gc];
                out[(size_t)(bb * Tsz + tt) * Vsz + gc] = val;
                sp[r * 20 + cc] = val;              // keep biased value for stats
            }
            __syncwarp();
            if (lane < 16) {
#pragma unroll
                for (int cc = 0; cc < 16; cc++) {
                    float v = sp[lane * 20 + cc];
                    if (v > rm) { rs = rs * __expf(rm - v) + 1.f; rm = v; }
                    else        { rs += __expf(v - rm); }
                }
            }
            __syncwarp();
        }
        if (lane < 16) {
            int row = wm * 64 + i * 16 + lane;
            srow[row * 8 + wn * 2]     = rm;
            srow[row * 8 + wn * 2 + 1] = rs;
        }
    }
    __syncthreads();
    for (int row = tid; row < 128; row += 256) {
        float M = srow[row * 8], S = srow[row * 8 + 1];
#pragma unroll
        for (int k = 1; k < 4; k++) {
            float m2 = srow[row * 8 + k * 2], s2 = srow[row * 8 + k * 2 + 1];
            float mm = fmaxf(M, m2);
            S = S * __expf(M - mm) + s2 * __expf(m2 - mm);
            M = mm;
        }
        int gr = m0 + row;
        int bb = gr & 63, tt = gr >> 6;
        g_part[(size_t)(bb * Tsz + tt) * 250 + blockIdx.x] = make_float2(M, S);
    }
}

// ---------------- normalize: merge partials, subtract L (single read+write pass) ----
__global__ __launch_bounds__(256) void k_norm(float* __restrict__ out) {
    int row = blockIdx.x;
    int tid = threadIdx.x;
    float M = -1e30f, S = 0.f;
    for (int i = tid; i < 250; i += 256) {
        float2 p = g_part[(size_t)row * 250 + i];
        float mm = fmaxf(M, p.x);
        S = S * __expf(M - mm) + p.y * __expf(p.x - mm);
        M = mm;
    }
    __shared__ float sm[256], ss[256];
    sm[tid] = M; ss[tid] = S;
    __syncthreads();
    for (int o = 128; o > 0; o >>= 1) {
        if (tid < o) {
            float m2 = sm[tid + o], s2 = ss[tid + o];
            float mm = fmaxf(sm[tid], m2);
            ss[tid] = ss[tid] * __expf(sm[tid] - mm) + s2 * __expf(m2 - mm);
            sm[tid] = mm;
        }
        __syncthreads();
    }
    float L = sm[0] + logf(ss[0]);
    float4* p4 = (float4*)(out + (size_t)row * Vsz);
    for (int j = tid; j < Vsz / 4; j += 256) {
        float4 v = p4[j];
        v.x -= L; v.y -= L; v.z -= L; v.w -= L;
        p4[j] = v;
    }
}

// ---------------- launch ----------------
extern "C" void kernel_launch(void* const* d_in, const int* in_sizes, int n_in,
                              void* d_out, int out_size) {
    const float* enc_out = (const float*)d_in[0];
    const float* enc_hid = (const float*)d_in[1];
    const int*   target  = (const int*)d_in[2];
    const float* embedding = (const float*)d_in[3];
    const float* Wa  = (const float*)d_in[4];
    const float* ba  = (const float*)d_in[5];
    const float* Ua  = (const float*)d_in[6];
    const float* bu  = (const float*)d_in[7];
    const float* Va  = (const float*)d_in[8];
    // d_in[9] = bv : softmax shift-invariant, unused
    const float* W_ih = (const float*)d_in[10];
    const float* W_hh = (const float*)d_in[11];
    const float* b_ih = (const float*)d_in[12];
    const float* b_hh = (const float*)d_in[13];
    const float* W_out = (const float*)d_in[14];
    const float* b_out = (const float*)d_in[15];

    float* out = (float*)d_out;
    float* out_dec  = out;                                        // [B,T,V]
    float* out_hid  = out + (size_t)Bsz * Tsz * Vsz;              // [1,B,H]
    float* out_attn = out_hid + (size_t)Bsz * Hsz;                // [B,T,S]

    cudaFuncSetAttribute(k_gemm_out, cudaFuncAttributeMaxDynamicSharedMemorySize,
                         8 * OUT_STAGE_B);

    // init
    k_round_all<<<1024, 256>>>(enc_out, Ua, Wa, W_hh, W_ih);
    k_embed_init<<<Tsz * Bsz + 256, 256>>>(target, embedding, enc_hid);
    k_wout_conv<<<2048, 256>>>(W_out);
    k_gemm_pre<<<512 + 960, NTHR>>>();

    // full recurrence in one launch
    k_persist<<<NBLK, NTHR>>>(enc_out, Va, ba, bu, b_ih, b_hh, out_attn, out_hid);

    // output projection (with fused softmax partials) + normalize
    {
        dim3 grid(Vsz / 128, (Tsz * Bsz) / 128);  // 250 x 20
        k_gemm_out<<<grid, 256, 8 * OUT_STAGE_B>>>(b_out, out_dec);
    }
    k_norm<<<Tsz * Bsz, 256>>>(out_dec);
}

// round 14
// speedup vs baseline: 1.0961x; 1.0161x over previous
#include <cuda_runtime.h>
#include <cuda_bf16.h>
#include <mma.h>
#include <cstdint>

using namespace nvcuda;

#define Bsz 64
#define Ssz 64
#define Hsz 1024
#define Vsz 32000
#define Tsz 40
#define NBLK 148
#define NTHR 256

// ---------------- scratch ----------------
__device__ float g_keysU[Bsz * Ssz * Hsz];          // 16 MB (bias added in persist)
__device__ float g_emb[Tsz * Bsz * Hsz];            // 10 MB [t][b][h] (tf32-rounded)
__device__ float g_h[Bsz * Hsz];                    // exact fp32 hidden
__device__ float g_h32[Bsz * Hsz];                  // tf32-rounded copy for GEMMs
__device__ float g_q4[4][Bsz * Hsz];                // q split-K parts
__device__ float g_gh2[2][Bsz * 3 * Hsz];           // gh split-K parts (K=512 x2)
__device__ float g_gc4[4][Bsz * 3 * Hsz];           // gi ctx-half split-K parts
__device__ float g_giE[(size_t)Tsz * Bsz * 3 * Hsz];// 31.5 MB
__device__ float g_ctx[Bsz * Hsz];                  // tf32-rounded at store
__device__ __nv_bfloat16 g_hall[Tsz * Bsz * Hsz];   // 5 MB
__device__ __nv_bfloat16 g_wout[Vsz * Hsz];         // 65 MB
// tf32-RN pre-rounded operand copies
__device__ float g_enc32[Bsz * Ssz * Hsz];          // 16 MB
__device__ float g_Ua32[Hsz * Hsz];
__device__ float g_Wa32[Hsz * Hsz];
__device__ float g_Whh32[3 * Hsz * Hsz];
__device__ float g_Wih32[3 * Hsz * 2 * Hsz];
__device__ unsigned g_barcnt = 0;
__device__ unsigned g_bargen = 0;
// dependency channels
__device__ unsigned g_ccnt[8];
__device__ volatile unsigned g_cgen[8];
#define CH_Q 0
#define CH_CTX 1
#define CH_D 2
#define CH_GH 3
#define CH_H 4

// fast activations
__device__ __forceinline__ float tanh_fast(float x) {
    float y; asm("tanh.approx.f32 %0, %1;" : "=f"(y) : "f"(x)); return y;
}
__device__ __forceinline__ float ftanh(float x) {
    float e = __expf(2.f * x);
    return 1.f - __fdividef(2.f, e + 1.f);
}
__device__ __forceinline__ float fsigmoid(float x) {
    return __fdividef(1.f, 1.f + __expf(-x));
}
__device__ __forceinline__ float rnd32(float x) {
    float y; asm("cvt.rna.tf32.f32 %0, %1;" : "=f"(y) : "f"(x)); return y;
}

// cp.async helpers
__device__ __forceinline__ void cp16(void* sdst, const void* gsrc) {
    unsigned s = (unsigned)__cvta_generic_to_shared(sdst);
    asm volatile("cp.async.cg.shared.global [%0], [%1], 16;\n" :: "r"(s), "l"(gsrc));
}
#define CP_COMMIT() asm volatile("cp.async.commit_group;\n")
#define CP_WAIT1()  asm volatile("cp.async.wait_group 1;\n")
#define CP_WAIT2()  asm volatile("cp.async.wait_group 2;\n")

// channel barrier primitives
__device__ __forceinline__ void ch_arrive(int ch, unsigned total, unsigned gen, int tid) {
    __syncthreads();
    if (tid == 0) {
        __threadfence();
        unsigned old = atomicAdd(&g_ccnt[ch], 1u);
        if (old == total - 1) {
            g_ccnt[ch] = 0;
            __threadfence();
            g_cgen[ch] = gen;
        }
    }
}
__device__ __forceinline__ void ch_wait(int ch, unsigned gen, int tid) {
    if (tid == 0) {
        while (g_cgen[ch] < gen) __nanosleep(32);
        __threadfence();
    }
    __syncthreads();
}
__device__ __forceinline__ void ch_wait2(int c0, int c1, unsigned gen, int tid) {
    if (tid == 0) {
        while (g_cgen[c0] < gen) __nanosleep(32);
        while (g_cgen[c1] < gen) __nanosleep(32);
        __threadfence();
    }
    __syncthreads();
}

// ---------------- init kernels ----------------
__global__ void k_round_all(const float* __restrict__ enc, const float* __restrict__ Ua,
                            const float* __restrict__ Wa, const float* __restrict__ Whh,
                            const float* __restrict__ Wih) {
    const int nEnc = Bsz * Ssz * Hsz / 4;
    const int nUa  = Hsz * Hsz / 4;
    const int nWhh = 3 * Hsz * Hsz / 4;
    const int nWih = 3 * Hsz * 2 * Hsz / 4;
    const int e0 = nEnc, e1 = e0 + nUa, e2 = e1 + nUa, e3 = e2 + nWhh, e4 = e3 + nWih;
    for (int i = blockIdx.x * blockDim.x + threadIdx.x; i < e4; i += gridDim.x * blockDim.x) {
        const float4* src; float4* dst;
        if (i < e0)      { src = (const float4*)enc + i;        dst = (float4*)g_enc32 + i; }
        else if (i < e1) { src = (const float4*)Ua + (i - e0);  dst = (float4*)g_Ua32 + (i - e0); }
        else if (i < e2) { src = (const float4*)Wa + (i - e1);  dst = (float4*)g_Wa32 + (i - e1); }
        else if (i < e3) { src = (const float4*)Whh + (i - e2); dst = (float4*)g_Whh32 + (i - e2); }
        else             { src = (const float4*)Wih + (i - e3); dst = (float4*)g_Wih32 + (i - e3); }
        float4 v = *src;
        v.x = rnd32(v.x); v.y = rnd32(v.y); v.z = rnd32(v.z); v.w = rnd32(v.w);
        *dst = v;
    }
}

__global__ void k_embed_init(const int* __restrict__ target, const float* __restrict__ emb,
                             const float* __restrict__ eh) {
    int bx = blockIdx.x;
    if (bx < Tsz * Bsz) {
        int t = bx / Bsz, b = bx % Bsz;
        int tok = (t == 0) ? 0 : target[b * Tsz + t - 1];
        const float4* src = (const float4*)(emb + (size_t)tok * Hsz);
        float4* dst = (float4*)(g_emb + ((size_t)t * Bsz + b) * Hsz);
        for (int j = threadIdx.x; j < Hsz / 4; j += blockDim.x) {
            float4 v = src[j];
            v.x = rnd32(v.x); v.y = rnd32(v.y); v.z = rnd32(v.z); v.w = rnd32(v.w);
            dst[j] = v;
        }
    } else {
        int i = (bx - Tsz * Bsz) * 256 + threadIdx.x;
        if (i < Bsz * Hsz) { g_h[i] = eh[i]; g_h32[i] = rnd32(eh[i]); }
    }
}

__global__ void k_wout_conv(const float* __restrict__ W) {
    int n4 = Vsz * Hsz / 4;
    for (int i = blockIdx.x * blockDim.x + threadIdx.x; i < n4; i += gridDim.x * blockDim.x) {
        float4 v = ((const float4*)W)[i];
        ((__nv_bfloat162*)g_wout)[2 * i]     = __floats2bfloat162_rn(v.x, v.y);
        ((__nv_bfloat162*)g_wout)[2 * i + 1] = __floats2bfloat162_rn(v.z, v.w);
    }
}

// ---------------- tf32 64x128 tile GEMM, cp.async 3-stage, BK=16 ----------------
__device__ __forceinline__ void gemm64x128(const float* __restrict__ A, int lda,
                                           const float* __restrict__ B, int ldb,
                                           float* __restrict__ C, int ldc,
                                           int kiters, float* sbuf) {
    float (*As)[64][20]  = (float(*)[64][20])sbuf;
    float (*Bs)[128][20] = (float(*)[128][20])(sbuf + 3 * 64 * 20);
    int tid = threadIdx.x;
    int ra = tid >> 2, ca = (tid & 3) << 2;
    int rb = tid >> 1, cb = (tid & 1) << 3;
    int warp = tid >> 5, wm = warp >> 2, wn = warp & 3;

    const float* Ap = A + (size_t)ra * lda + ca;
    const float* Bp = B + (size_t)rb * ldb + cb;

    wmma::fragment<wmma::accumulator, 16, 16, 8, float> acc[2][2];
#pragma unroll
    for (int i = 0; i < 2; i++)
#pragma unroll
        for (int j = 0; j < 2; j++) wmma::fill_fragment(acc[i][j], 0.f);

#pragma unroll
    for (int s = 0; s < 2; s++) {
        if (s < kiters) {
            cp16(&As[s][ra][ca], Ap + s * 16);
            cp16(&Bs[s][rb][cb], Bp + s * 16);
            cp16(&Bs[s][rb][cb + 4], Bp + s * 16 + 4);
        }
        CP_COMMIT();
    }

    int stg = 2;
    for (int it = 0; it < kiters; it++) {
        int cur = it % 3;
        CP_WAIT1();
        __syncthreads();
        if (it + 2 < kiters) {
            cp16(&As[stg][ra][ca], Ap + (it + 2) * 16);
            cp16(&Bs[stg][rb][cb], Bp + (it + 2) * 16);
            cp16(&Bs[stg][rb][cb + 4], Bp + (it + 2) * 16 + 4);
        }
        CP_COMMIT();
        stg++; if (stg == 3) stg = 0;
#pragma unroll
        for (int ks = 0; ks < 2; ks++) {
            wmma::fragment<wmma::matrix_a, 16, 16, 8, wmma::precision::tf32, wmma::row_major> af0, af1;
            wmma::fragment<wmma::matrix_b, 16, 16, 8, wmma::precision::tf32, wmma::col_major> bf0, bf1;
            wmma::load_matrix_sync(af0, &As[cur][wm * 32][ks * 8], 20);
            wmma::load_matrix_sync(af1, &As[cur][wm * 32 + 16][ks * 8], 20);
            wmma::load_matrix_sync(bf0, &Bs[cur][wn * 32][ks * 8], 20);
            wmma::load_matrix_sync(bf1, &Bs[cur][wn * 32 + 16][ks * 8], 20);
            wmma::mma_sync(acc[0][0], af0, bf0, acc[0][0]);
            wmma::mma_sync(acc[0][1], af0, bf1, acc[0][1]);
            wmma::mma_sync(acc[1][0], af1, bf0, acc[1][0]);
            wmma::mma_sync(acc[1][1], af1, bf1, acc[1][1]);
        }
    }
    __syncthreads();
#pragma unroll
    for (int i = 0; i < 2; i++)
#pragma unroll
        for (int j = 0; j < 2; j++)
            wmma::store_matrix_sync(C + (size_t)(wm * 32 + i * 16) * ldc + wn * 32 + j * 16,
                                    acc[i][j], ldc, wmma::mem_row_major);
}

// merged precompute: keysU (512 tiles) + giE (960 tiles)
__global__ __launch_bounds__(NTHR, 3) void k_gemm_pre() {
    __shared__ float sbuf[11520];
    int bx = blockIdx.x;
    if (bx < 512) {
        int nt = bx & 7, mt = bx >> 3;
        int m0 = mt * 64, n0 = nt * 128;
        gemm64x128(g_enc32 + (size_t)m0 * Hsz, Hsz, g_Ua32 + (size_t)n0 * Hsz, Hsz,
                   g_keysU + (size_t)m0 * Hsz + n0, Hsz, 64, sbuf);
    } else {
        int idx = bx - 512;
        int nt = idx % 24, t = idx / 24;
        int n0 = nt * 128;
        gemm64x128(g_emb + (size_t)t * Bsz * Hsz, Hsz,
                   g_Wih32 + (size_t)n0 * (2 * Hsz), 2 * Hsz,
                   g_giE + (size_t)t * Bsz * 3 * Hsz + n0, 3 * Hsz, 64, sbuf);
    }
}

// ---------------- persistent recurrence kernel (R9 3319us structure) ----------------
__global__ __launch_bounds__(NTHR, 1) void k_persist(
    const float* __restrict__ enc, const float* __restrict__ Va,
    const float* __restrict__ ba, const float* __restrict__ bu,
    const float* __restrict__ b_ih, const float* __restrict__ b_hh,
    float* __restrict__ out_attn, float* __restrict__ out_hid)
{
    __shared__ float sbuf[11520];
    __shared__ unsigned s_gen0;
    int tid = threadIdx.x;
    int bx = blockIdx.x;
    if (tid == 0) s_gen0 = *((volatile unsigned*)&g_bargen);
    __syncthreads();
    unsigned gen = s_gen0;

    auto gbar = [&]() {
        gen++;
        __syncthreads();
        if (tid == 0) {
            __threadfence();
            unsigned a = atomicAdd(&g_barcnt, 1u);
            if (a == NBLK - 1) {
                g_barcnt = 0;
                __threadfence();
                *((volatile unsigned*)&g_bargen) = gen;
            } else {
                while (*((volatile unsigned*)&g_bargen) != gen) __nanosleep(32);
                __threadfence();
            }
        }
        __syncthreads();
    };

    // pre-phase: fold attention biases into keysU; reset channels
    for (int i = bx * NTHR + tid; i < Bsz * Ssz * Hsz; i += NBLK * NTHR) {
        int n = i & (Hsz - 1);
        g_keysU[i] += ba[n] + bu[n];
    }
    gbar();
    if (bx == 0 && tid == 0) {
#pragma unroll
        for (int c = 0; c < 8; c++) { g_ccnt[c] = 0; g_cgen[c] = 0; }
    }
    gbar();

    for (int t = 0; t < Tsz; t++) {
        unsigned g = (unsigned)t + 1;

        // ---- q: blocks 0-31 (8 n-tiles x split-K4, K=256) ----
        if (bx < 32) {
            ch_wait(CH_H, (unsigned)t, tid);
            int jt = bx >> 2, kh = bx & 3, n0 = jt * 128;
            gemm64x128(g_h32 + kh * 256, Hsz,
                       g_Wa32 + (size_t)n0 * Hsz + kh * 256, Hsz,
                       g_q4[kh] + n0, Hsz, 16, sbuf);
            ch_arrive(CH_Q, 32, g, tid);
        }

        // ---- gh: blocks 100-147 (24 n-tiles x split-K2, K=512), overlaps BC/D ----
        if (bx >= 100) {
            ch_wait(CH_H, (unsigned)t, tid);
            int idx = bx - 100, jt = idx >> 1, kh = idx & 1, n0 = jt * 128;
            gemm64x128(g_h32 + kh * 512, Hsz,
                       g_Whh32 + (size_t)n0 * Hsz + kh * 512, Hsz,
                       g_gh2[kh] + n0, 3 * Hsz, 32, sbuf);
            ch_arrive(CH_GH, 48, g, tid);
        }

        // ---- BC: scores + softmax + ctx, blocks 0-63 (smem-cached q row) ----
        if (bx < 64) {
            ch_wait(CH_Q, g, tid);
            int b = bx;
            float* qs = sbuf;
            float* va = sbuf + 1024;
            float* sc = sbuf + 2048;
            float* ws = sbuf + 2112;
            for (int j = tid; j < Hsz; j += NTHR) {
                qs[j] = g_q4[0][b * Hsz + j] + g_q4[1][b * Hsz + j]
                      + g_q4[2][b * Hsz + j] + g_q4[3][b * Hsz + j];
                va[j] = Va[j];
            }
            __syncthreads();
            int w = tid >> 5, lane = tid & 31;
#pragma unroll
            for (int si = 0; si < 8; si++) {
                int s = w * 8 + si;
                const float* kp = g_keysU + (size_t)(b * Ssz + s) * Hsz;
                float acc = 0.f;
#pragma unroll 8
                for (int jj = 0; jj < 32; jj++) {
                    int j = lane + jj * 32;
                    acc += va[j] * tanh_fast(qs[j] + kp[j]);
                }
#pragma unroll
                for (int o = 16; o > 0; o >>= 1) acc += __shfl_xor_sync(0xffffffffu, acc, o);
                if (lane == 0) sc[s] = acc;
            }
            __syncthreads();
            if (w == 0) {
                float v0 = sc[lane], v1 = sc[lane + 32];
                float m = fmaxf(v0, v1);
#pragma unroll
                for (int o = 16; o > 0; o >>= 1) m = fmaxf(m, __shfl_xor_sync(0xffffffffu, m, o));
                float e0 = __expf(v0 - m), e1 = __expf(v1 - m);
                float ssum = e0 + e1;
#pragma unroll
                for (int o = 16; o > 0; o >>= 1) ssum += __shfl_xor_sync(0xffffffffu, ssum, o);
                float inv = __fdividef(1.f, ssum);
                ws[lane] = e0 * inv;
                ws[lane + 32] = e1 * inv;
            }
            __syncthreads();
            if (tid < Ssz) out_attn[(size_t)b * Tsz * Ssz + t * Ssz + tid] = ws[tid];
            float c0 = 0.f, c1 = 0.f, c2 = 0.f, c3 = 0.f;
            const float* ep = enc + (size_t)b * Ssz * Hsz + tid;
#pragma unroll 4
            for (int s = 0; s < Ssz; s++) {
                float wv = ws[s];
                const float* row = ep + (size_t)s * Hsz;
                c0 += wv * row[0];
                c1 += wv * row[256];
                c2 += wv * row[512];
                c3 += wv * row[768];
            }
            g_ctx[b * Hsz + tid]       = rnd32(c0);
            g_ctx[b * Hsz + tid + 256] = rnd32(c1);
            g_ctx[b * Hsz + tid + 512] = rnd32(c2);
            g_ctx[b * Hsz + tid + 768] = rnd32(c3);
            ch_arrive(CH_CTX, 64, g, tid);
        }

        // ---- D: gi_ctx = ctx @ W_ih[:, H:2H]^T, blocks 0-95 (24 n-tiles x split-K4) ----
        if (bx < 96) {
            ch_wait(CH_CTX, g, tid);
            int jt = bx >> 2, kh = bx & 3, n0 = jt * 128;
            gemm64x128(g_ctx + kh * 256, Hsz,
                       g_Wih32 + (size_t)n0 * (2 * Hsz) + Hsz + kh * 256, 2 * Hsz,
                       g_gc4[kh] + n0, 3 * Hsz, 16, sbuf);
            ch_arrive(CH_D, 96, g, tid);
        }

        // ---- E: gates + h update, all blocks ----
        ch_wait2(CH_D, CH_GH, g, tid);
        {
            const float* giE = g_giE + (size_t)t * Bsz * 3 * Hsz;
            for (int i = bx * NTHR + tid; i < Bsz * Hsz; i += NBLK * NTHR) {
                int b = i >> 10, j = i & (Hsz - 1);
                size_t base3 = (size_t)b * 3 * Hsz;
                float ir = giE[base3 + j] + b_ih[j];
                float iz = giE[base3 + Hsz + j] + b_ih[Hsz + j];
                float in = giE[base3 + 2 * Hsz + j] + b_ih[2 * Hsz + j];
#pragma unroll
                for (int kh = 0; kh < 4; kh++) {
                    ir += g_gc4[kh][base3 + j];
                    iz += g_gc4[kh][base3 + Hsz + j];
                    in += g_gc4[kh][base3 + 2 * Hsz + j];
                }
                float hr = b_hh[j]           + g_gh2[0][base3 + j]           + g_gh2[1][base3 + j];
                float hz = b_hh[Hsz + j]     + g_gh2[0][base3 + Hsz + j]     + g_gh2[1][base3 + Hsz + j];
                float hn = b_hh[2 * Hsz + j] + g_gh2[0][base3 + 2 * Hsz + j] + g_gh2[1][base3 + 2 * Hsz + j];
                float rr = fsigmoid(ir + hr);
                float zz = fsigmoid(iz + hz);
                float nn = ftanh(in + rr * hn);
                float hp = g_h[i];
                float hnew = (1.f - zz) * nn + zz * hp;
                g_h[i] = hnew;
                g_h32[i] = rnd32(hnew);
                g_hall[((size_t)t * Bsz + b) * Hsz + j] = __float2bfloat16(hnew);
            }
        }
        ch_arrive(CH_H, NBLK, g, tid);
    }

    for (int i = bx * NTHR + tid; i < Bsz * Hsz; i += NBLK * NTHR)
        out_hid[i] = g_h[i];
}

// ---------------- output projection: logits = Hall @ Wout^T + b_out ----------------
#define OUT_STAGE_B 10240
__global__ __launch_bounds__(256, 2) void k_gemm_out(const float* __restrict__ b_out,
                                                     float* __restrict__ out) {
    extern __shared__ char dyn[];
    char* sA = dyn;
    char* sB = dyn + 4 * OUT_STAGE_B;
    const int K = Hsz;
    int m0 = blockIdx.y * 128, n0 = blockIdx.x * 128;
    int tid = threadIdx.x;
    int warp = tid >> 5, lane = tid & 31;
    int wm = warp >> 2, wn = warp & 3;

    const char* Ag = (const char*)(g_hall + (size_t)m0 * K);
    const char* Bg = (const char*)(g_wout + (size_t)n0 * K);

    int c0 = tid * 2;
    int rowA0 = c0 >> 2, off0 = (c0 & 3) * 16;
    int rowA1 = (c0 + 1) >> 2, off1 = ((c0 + 1) & 3) * 16;

    auto load_stage = [&](int kt, int s) {
        char* dA = sA + s * OUT_STAGE_B;
        char* dB = sB + s * OUT_STAGE_B;
        const char* a0 = Ag + (size_t)rowA0 * (K * 2) + kt * 64 + off0;
        const char* a1 = Ag + (size_t)rowA1 * (K * 2) + kt * 64 + off1;
        const char* b0 = Bg + (size_t)rowA0 * (K * 2) + kt * 64 + off0;
        const char* b1 = Bg + (size_t)rowA1 * (K * 2) + kt * 64 + off1;
        cp16(dA + rowA0 * 80 + off0, a0);
        cp16(dA + rowA1 * 80 + off1, a1);
        cp16(dB + rowA0 * 80 + off0, b0);
        cp16(dB + rowA1 * 80 + off1, b1);
        CP_COMMIT();
    };

    wmma::fragment<wmma::accumulator, 16, 16, 16, float> acc[4][2];
#pragma unroll
    for (int i = 0; i < 4; i++)
#pragma unroll
        for (int j = 0; j < 2; j++) wmma::fill_fragment(acc[i][j], 0.f);

    load_stage(0, 0);
    load_stage(1, 1);
    load_stage(2, 2);

    const int NKT = K / 32;
    for (int kt = 0; kt < NKT; kt++) {
        int cur = kt & 3;
        CP_WAIT2();
        __syncthreads();
        if (kt + 3 < NKT) load_stage(kt + 3, (kt + 3) & 3);
        else CP_COMMIT();
        const __nv_bfloat16* As = (const __nv_bfloat16*)(sA + cur * OUT_STAGE_B);
        const __nv_bfloat16* Bs = (const __nv_bfloat16*)(sB + cur * OUT_STAGE_B);
#pragma unroll
        for (int ks = 0; ks < 2; ks++) {
            wmma::fragment<wmma::matrix_a, 16, 16, 16, __nv_bfloat16, wmma::row_major> af[4];
            wmma::fragment<wmma::matrix_b, 16, 16, 16, __nv_bfloat16, wmma::col_major> bf[2];
#pragma unroll
            for (int i = 0; i < 4; i++)
                wmma::load_matrix_sync(af[i], As + (wm * 64 + i * 16) * 40 + ks * 16, 40);
#pragma unroll
            for (int j = 0; j < 2; j++)
                wmma::load_matrix_sync(bf[j], Bs + (wn * 32 + j * 16) * 40 + ks * 16, 40);
#pragma unroll
            for (int i = 0; i < 4; i++)
#pragma unroll
                for (int j = 0; j < 2; j++)
                    wmma::mma_sync(acc[i][j], af[i], bf[j], acc[i][j]);
        }
    }
    __syncthreads();

    float* stage = (float*)dyn;
    float* sp = stage + warp * 320;
#pragma unroll
    for (int i = 0; i < 4; i++) {
#pragma unroll
        for (int j = 0; j < 2; j++) {
            wmma::store_matrix_sync(sp, acc[i][j], 20, wmma::mem_row_major);
            __syncwarp();
            int gr0 = m0 + wm * 64 + i * 16;
            int gc0 = n0 + wn * 32 + j * 16;
            for (int e = lane; e < 256; e += 32) {
                int r = e >> 4, cc = e & 15;
                int gr = gr0 + r, gc = gc0 + cc;
                int bb = gr & 63, tt = gr >> 6;
                out[(size_t)(bb * Tsz + tt) * Vsz + gc] = sp[r * 20 + cc] + b_out[gc];
            }
            __syncwarp();
        }
    }
}

// ---------------- in-place log_softmax (float4) ----------------
__global__ __launch_bounds__(256) void k_logsoftmax(float* __restrict__ out) {
    int row = blockIdx.x;
    float4* p4 = (float4*)(out + (size_t)row * Vsz);
    const int N4 = Vsz / 4;
    int tid = threadIdx.x;
    float m = -1e30f, s = 0.f;
    for (int j = tid; j < N4; j += 256) {
        float4 v = p4[j];
        float vm = fmaxf(fmaxf(v.x, v.y), fmaxf(v.z, v.w));
        if (vm > m) { s = s * __expf(m - vm); m = vm; }
        s += __expf(v.x - m) + __expf(v.y - m) + __expf(v.z - m) + __expf(v.w - m);
    }
    __shared__ float sm[256], ss[256];
    sm[tid] = m; ss[tid] = s;
    __syncthreads();
    for (int o = 128; o > 0; o >>= 1) {
        if (tid < o) {
            float m2 = sm[tid + o], s2 = ss[tid + o];
            float mm = fmaxf(sm[tid], m2);
            ss[tid] = ss[tid] * __expf(sm[tid] - mm) + s2 * __expf(m2 - mm);
            sm[tid] = mm;
        }
        __syncthreads();
    }
    float L = sm[0] + logf(ss[0]);
    for (int j = tid; j < N4; j += 256) {
        float4 v = p4[j];
        v.x -= L; v.y -= L; v.z -= L; v.w -= L;
        p4[j] = v;
    }
}

// ---------------- launch ----------------
extern "C" void kernel_launch(void* const* d_in, const int* in_sizes, int n_in,
                              void* d_out, int out_size) {
    const float* enc_out = (const float*)d_in[0];
    const float* enc_hid = (const float*)d_in[1];
    const int*   target  = (const int*)d_in[2];
    const float* embedding = (const float*)d_in[3];
    const float* Wa  = (const float*)d_in[4];
    const float* ba  = (const float*)d_in[5];
    const float* Ua  = (const float*)d_in[6];
    const float* bu  = (const float*)d_in[7];
    const float* Va  = (const float*)d_in[8];
    // d_in[9] = bv : softmax shift-invariant, unused
    const float* W_ih = (const float*)d_in[10];
    const float* W_hh = (const float*)d_in[11];
    const float* b_ih = (const float*)d_in[12];
    const float* b_hh = (const float*)d_in[13];
    const float* W_out = (const float*)d_in[14];
    const float* b_out = (const float*)d_in[15];

    float* out = (float*)d_out;
    float* out_dec  = out;                                        // [B,T,V]
    float* out_hid  = out + (size_t)Bsz * Tsz * Vsz;              // [1,B,H]
    float* out_attn = out_hid + (size_t)Bsz * Hsz;                // [B,T,S]

    // one-time resources (created on first, non-captured, correctness call)
    static cudaStream_t s2 = nullptr;
    static cudaEvent_t evFork = nullptr, evEmb = nullptr, evWout = nullptr;
    if (s2 == nullptr) {
        cudaStreamCreateWithFlags(&s2, cudaStreamNonBlocking);
        cudaEventCreateWithFlags(&evFork, cudaEventDisableTiming);
        cudaEventCreateWithFlags(&evEmb, cudaEventDisableTiming);
        cudaEventCreateWithFlags(&evWout, cudaEventDisableTiming);
        cudaFuncSetAttribute(k_gemm_out, cudaFuncAttributeMaxDynamicSharedMemorySize,
                             8 * OUT_STAGE_B);
    }

    // fork side stream: embed/h-init then wout conversion (independent chains)
    cudaEventRecord(evFork, 0);
    cudaStreamWaitEvent(s2, evFork, 0);
    k_embed_init<<<Tsz * Bsz + 256, 256, 0, s2>>>(target, embedding, enc_hid);
    cudaEventRecord(evEmb, s2);
    k_wout_conv<<<2048, 256, 0, s2>>>(W_out);
    cudaEventRecord(evWout, s2);

    // main chain
    k_round_all<<<1024, 256>>>(enc_out, Ua, Wa, W_hh, W_ih);
    cudaStreamWaitEvent(0, evEmb, 0);      // gemm_pre needs g_emb (+ g_h32 for persist)
    k_gemm_pre<<<512 + 960, NTHR>>>();
    k_persist<<<NBLK, NTHR>>>(enc_out, Va, ba, bu, b_ih, b_hh, out_attn, out_hid);
    cudaStreamWaitEvent(0, evWout, 0);     // gemm_out needs g_wout
    {
        dim3 grid(Vsz / 128, (Tsz * Bsz) / 128);  // 250 x 20
        k_gemm_out<<<grid, 256, 8 * OUT_STAGE_B>>>(b_out, out_dec);
    }
    k_logsoftmax<<<Tsz * Bsz, 256>>>(out_dec);
}